// round 1
// baseline (speedup 1.0000x reference)
#include <cuda_runtime.h>
#include <math.h>

#define BSZ   16
#define NTOT  8208
#define HD    768
#define NG    5
#define NM    96          // 16 q rows + 80 (q*inv_g) rows

// output offsets (flattened concat of the 8 reference outputs, float32)
#define OFF_GLOG 0
#define OFF_GPRB 656640
#define OFF_CLOG 1313280
#define OFF_ACC  1444608
#define OFF_NRM  1575936
#define OFF_GLBL 1575941
#define OFF_CLBL 1707269
#define OFF_CDST 1838597

__device__ float g_W[NM * HD];
__device__ float g_inv[NG * HD];
__device__ float g_muinv[NG * HD];
__device__ float g_Cbg[BSZ * NG];
__device__ float g_SaaSam[NTOT * 10];
__device__ float g_S[NM * NTOT];
__device__ float g_rowmax[BSZ];
__device__ float g_cnt[NG];
__device__ float g_sum[NG];

__device__ __forceinline__ float wred(float v) {
    #pragma unroll
    for (int o = 16; o; o >>= 1) v += __shfl_down_sync(0xffffffffu, v, o);
    return v;
}

// ---------------------------------------------------------------------------
// K1: prep — inv, mu*inv, W (96 rows), per-(b,g) constants, zero accumulators
// ---------------------------------------------------------------------------
__global__ void prep_kernel(const float* __restrict__ q,
                            const float* __restrict__ mu,
                            const float* __restrict__ lgs,
                            const float* __restrict__ pi) {
    const int tid = threadIdx.x;
    __shared__ float s_lse;
    __shared__ float s_sqq[80], s_sqm[80], s_smm[NG], s_slg[NG];

    if (tid == 0) {
        float m = pi[0];
        for (int g = 1; g < NG; g++) m = fmaxf(m, pi[g]);
        float s = 0.f;
        for (int g = 0; g < NG; g++) s += expf(pi[g] - m);
        s_lse = m + logf(s);
    }
    if (tid < NG) { g_cnt[tid] = 0.f; g_sum[tid] = 0.f; }

    for (int i = tid; i < NG * HD; i += 256) {
        float v = expf(-lgs[i]);
        g_inv[i]   = v;
        g_muinv[i] = mu[i] * v;
    }
    __syncthreads();

    for (int i = tid; i < NM * HD; i += 256) {
        int m = i / HD, h = i - m * HD;
        float w;
        if (m < BSZ) w = q[m * HD + h];
        else {
            int bg = m - BSZ;
            int b = bg / NG, g = bg - b * NG;
            w = q[b * HD + h] * g_inv[g * HD + h];
        }
        g_W[i] = w;
    }

    const int warp = tid >> 5, lane = tid & 31;
    for (int p = warp; p < 80; p += 8) {
        int b = p / NG, g = p - b * NG;
        float a1 = 0.f, a2 = 0.f;
        for (int h = lane; h < HD; h += 32) {
            float qv = q[b * HD + h];
            a1 += qv * qv * g_inv[g * HD + h];
            a2 += qv * g_muinv[g * HD + h];
        }
        a1 = wred(a1); a2 = wred(a2);
        if (lane == 0) { s_sqq[p] = a1; s_sqm[p] = a2; }
    }
    if (warp < NG) {
        int g = warp;
        float a1 = 0.f, a2 = 0.f;
        for (int h = lane; h < HD; h += 32) {
            a1 += mu[g * HD + h] * g_muinv[g * HD + h];
            a2 += lgs[g * HD + h];
        }
        a1 = wred(a1); a2 = wred(a2);
        if (lane == 0) { s_smm[g] = a1; s_slg[g] = a2; }
    }
    __syncthreads();

    if (tid < 80) {
        int g = tid % NG;
        const float LG2PID = 768.0f * 1.8378770351409912f;
        float logpi = pi[g] - s_lse;
        g_Cbg[tid] = logpi - 0.5f * (LG2PID + s_slg[g] + s_sqq[tid] + s_smm[g]) + s_sqm[tid];
    }
}

// ---------------------------------------------------------------------------
// K2: per-n Saa[g] = sum a^2*inv_g ; Sam[g] = sum a*mu*inv_g  (warp per n)
// ---------------------------------------------------------------------------
__global__ void saasam_kernel(const float* __restrict__ sk,
                              const float* __restrict__ qu) {
    int warp = (blockIdx.x * blockDim.x + threadIdx.x) >> 5;
    int lane = threadIdx.x & 31;
    if (warp >= NTOT) return;
    const float* a = (warp < BSZ) ? (sk + warp * HD) : (qu + (warp - BSZ) * HD);
    float saa[NG] = {0, 0, 0, 0, 0}, sam[NG] = {0, 0, 0, 0, 0};
    for (int h = lane; h < HD; h += 32) {
        float v = a[h], v2 = v * v;
        #pragma unroll
        for (int g = 0; g < NG; g++) {
            saa[g] += v2 * g_inv[g * HD + h];
            sam[g] += v  * g_muinv[g * HD + h];
        }
    }
    #pragma unroll
    for (int g = 0; g < NG; g++) { saa[g] = wred(saa[g]); sam[g] = wred(sam[g]); }
    if (lane == 0) {
        #pragma unroll
        for (int g = 0; g < NG; g++) {
            g_SaaSam[warp * 10 + g]     = saa[g];
            g_SaaSam[warp * 10 + 5 + g] = sam[g];
        }
    }
}

// ---------------------------------------------------------------------------
// K3: SGEMM  g_S[96][8208] = g_W[96][768] @ all_feature^T
//     BM=96 BN=64 BK=16, 256 threads, 6x4 micro-tile, reg-prefetch pipelining
// ---------------------------------------------------------------------------
#define BKk 16
#define ASTR 98
#define BSTR 68

__global__ __launch_bounds__(256) void gemm_kernel(const float* __restrict__ sk,
                                                   const float* __restrict__ qu) {
    __shared__ float As[BKk * ASTR];
    __shared__ float Bs[BKk * BSTR];
    const int tid = threadIdx.x;
    const int n0  = blockIdx.x * 64;
    const int tr  = tid >> 4;      // 0..15  -> rows tr*6 .. tr*6+5
    const int tc  = tid & 15;      // 0..15  -> cols tc*4 .. tc*4+3

    float acc[6][4];
    #pragma unroll
    for (int i = 0; i < 6; i++)
        #pragma unroll
        for (int j = 0; j < 4; j++) acc[i][j] = 0.f;

    float pa[6], pb[4];
    // load tile 0
    #pragma unroll
    for (int j = 0; j < 6; j++) {
        int e = tid + j * 256; int k = e & 15, m = e >> 4;
        pa[j] = g_W[m * HD + k];
    }
    #pragma unroll
    for (int j = 0; j < 4; j++) {
        int e = tid + j * 256; int k = e & 15, n = e >> 4;
        int gn = n0 + n;
        float v = 0.f;
        if (gn < NTOT) {
            const float* src = (gn < BSZ) ? (sk + gn * HD) : (qu + (gn - BSZ) * HD);
            v = src[k];
        }
        pb[j] = v;
    }

    for (int s = 0; s < HD / BKk; s++) {
        #pragma unroll
        for (int j = 0; j < 6; j++) {
            int e = tid + j * 256; int k = e & 15, m = e >> 4;
            As[k * ASTR + m] = pa[j];
        }
        #pragma unroll
        for (int j = 0; j < 4; j++) {
            int e = tid + j * 256; int k = e & 15, n = e >> 4;
            Bs[k * BSTR + n] = pb[j];
        }
        __syncthreads();

        if (s < HD / BKk - 1) {
            int k0 = (s + 1) * BKk;
            #pragma unroll
            for (int j = 0; j < 6; j++) {
                int e = tid + j * 256; int k = e & 15, m = e >> 4;
                pa[j] = g_W[m * HD + k0 + k];
            }
            #pragma unroll
            for (int j = 0; j < 4; j++) {
                int e = tid + j * 256; int k = e & 15, n = e >> 4;
                int gn = n0 + n;
                float v = 0.f;
                if (gn < NTOT) {
                    const float* src = (gn < BSZ) ? (sk + gn * HD) : (qu + (gn - BSZ) * HD);
                    v = src[k0 + k];
                }
                pb[j] = v;
            }
        }

        #pragma unroll
        for (int k = 0; k < BKk; k++) {
            float2 a0 = *(const float2*)&As[k * ASTR + tr * 6];
            float2 a1 = *(const float2*)&As[k * ASTR + tr * 6 + 2];
            float2 a2 = *(const float2*)&As[k * ASTR + tr * 6 + 4];
            float4 bv = *(const float4*)&Bs[k * BSTR + tc * 4];
            float av[6] = {a0.x, a0.y, a1.x, a1.y, a2.x, a2.y};
            float bb[4] = {bv.x, bv.y, bv.z, bv.w};
            #pragma unroll
            for (int i = 0; i < 6; i++)
                #pragma unroll
                for (int j = 0; j < 4; j++) acc[i][j] = fmaf(av[i], bb[j], acc[i][j]);
        }
        __syncthreads();
    }

    #pragma unroll
    for (int i = 0; i < 6; i++) {
        int m = tr * 6 + i;
        #pragma unroll
        for (int j = 0; j < 4; j++) {
            int n = n0 + tc * 4 + j;
            if (n < NTOT) g_S[m * NTOT + n] = acc[i][j];
        }
    }
}

// ---------------------------------------------------------------------------
// K4a: per-b max over sample_sim row
// ---------------------------------------------------------------------------
__global__ void rowmax_kernel() {
    const int b = blockIdx.x;
    const int tid = threadIdx.x;
    __shared__ float sm[256];
    float m = -3.4e38f;
    for (int n = tid; n < NTOT; n += 256) m = fmaxf(m, g_S[b * NTOT + n]);
    sm[tid] = m;
    __syncthreads();
    for (int o = 128; o; o >>= 1) {
        if (tid < o) sm[tid] = fmaxf(sm[tid], sm[tid + o]);
        __syncthreads();
    }
    if (tid == 0) g_rowmax[b] = sm[0];
}

// ---------------------------------------------------------------------------
// K4: fused epilogue over all (b, n) cells
// ---------------------------------------------------------------------------
__global__ __launch_bounds__(256) void epi_kernel(const float* __restrict__ rank_mean,
                                                  float* __restrict__ out) {
    __shared__ float s_cnt[NG], s_sum[NG];
    const int tid = threadIdx.x;
    if (tid < NG) { s_cnt[tid] = 0.f; s_sum[tid] = 0.f; }
    __syncthreads();

    const int idx = blockIdx.x * 256 + tid;          // grid sized exactly
    const int b = idx / NTOT;
    const int n = idx - b * NTOT;

    const float sim = g_S[b * NTOT + n];

    float lg[NG], ev[NG];
    #pragma unroll
    for (int g = 0; g < NG; g++) {
        float Sqa = g_S[(BSZ + b * NG + g) * NTOT + n];
        float Saa = g_SaaSam[n * 10 + g];
        float Sam = g_SaaSam[n * 10 + 5 + g];
        lg[g] = g_Cbg[b * NG + g] + Sqa - 0.5f * Saa - Sam;
    }
    float m = lg[0]; int bi = 0;
    #pragma unroll
    for (int g = 1; g < NG; g++) if (lg[g] > m) { m = lg[g]; bi = g; }

    float sum = 0.f;
    #pragma unroll
    for (int g = 0; g < NG; g++) {
        float ln = lg[g] - m;
        out[OFF_GLOG + (size_t)idx * NG + g] = ln;
        float e = __expf(ln);
        ev[g] = e; sum += e;
    }
    float isum = 1.f / sum;
    #pragma unroll
    for (int g = 0; g < NG; g++)
        out[OFF_GPRB + (size_t)idx * NG + g] = ev[g] * isum;

    // cts_pred = argmin |sim - rank_mean|
    float bd = fabsf(sim - rank_mean[0]); int cp = 0;
    #pragma unroll
    for (int g = 1; g < NG; g++) {
        float d = fabsf(sim - rank_mean[g]);
        if (d < bd) { bd = d; cp = g; }
    }
    int cd = (int)floorf((sim + 1.0f) / 2.0f * 5.0f);

    bool golden = (n < BSZ) && (n == ((b + 8) & 15));
    bool eye    = (n == b);

    out[OFF_CLOG + idx] = sim - g_rowmax[b];
    out[OFF_ACC  + idx] = eye ? 0.f : sim;
    out[OFF_GLBL + idx] = (float)((eye || golden) ? (NG - 1) : cp);
    out[OFF_CLBL + idx] = (float)(golden ? (NG - 1) : bi);
    out[OFF_CDST + idx] = (float)cd;

    // rank-mean stats use gmm_pred BEFORE masking
    atomicAdd(&s_cnt[bi], 1.f);
    atomicAdd(&s_sum[bi], sim);
    __syncthreads();
    if (tid < NG) {
        atomicAdd(&g_cnt[tid], s_cnt[tid]);
        atomicAdd(&g_sum[tid], s_sum[tid]);
    }
}

// ---------------------------------------------------------------------------
// K5: rank-mean EMA finalize
// ---------------------------------------------------------------------------
__global__ void finish_kernel(const float* __restrict__ rank_mean,
                              float* __restrict__ out) {
    int g = threadIdx.x;
    if (g < NG) {
        float c = g_cnt[g], s = g_sum[g];
        float cur = s / (c + 1e-12f);
        float upd = (c != 0.f) ? 1.f : 0.f;
        out[OFF_NRM + g] = (1.f - upd * 0.1f) * rank_mean[g] + upd * 0.1f * cur;
    }
}

// ---------------------------------------------------------------------------
extern "C" void kernel_launch(void* const* d_in, const int* in_sizes, int n_in,
                              void* d_out, int out_size) {
    const float* sent_q    = (const float*)d_in[0];
    const float* sent_k    = (const float*)d_in[1];
    const float* queue     = (const float*)d_in[2];
    const float* mu        = (const float*)d_in[3];
    const float* lg_sigma2 = (const float*)d_in[4];
    const float* pi        = (const float*)d_in[5];
    const float* rank_mean = (const float*)d_in[6];
    float* out = (float*)d_out;

    prep_kernel<<<1, 256>>>(sent_q, mu, lg_sigma2, pi);
    saasam_kernel<<<(NTOT * 32 + 255) / 256, 256>>>(sent_k, queue);
    gemm_kernel<<<(NTOT + 63) / 64, 256>>>(sent_k, queue);
    rowmax_kernel<<<BSZ, 256>>>();
    epi_kernel<<<(BSZ * NTOT) / 256, 256>>>(rank_mean, out);
    finish_kernel<<<1, 32>>>(rank_mean, out);
}